// round 2
// baseline (speedup 1.0000x reference)
#include <cuda_runtime.h>

#define N_POS   4096
#define HEADS   4
#define DHEAD   32
#define C_IN    256
#define HID     128          // HEADS*DHEAD
#define BATCH   4
#define SCALE   10.0f

// Scratch (no cudaMalloc allowed): qkv [b][3*128][n], attn-out [b][128][n]
__device__ float g_qkv[(size_t)BATCH * 3 * HID * N_POS];   // 25.2 MB
__device__ float g_att[(size_t)BATCH * HID * N_POS];       //  8.4 MB

// ---------------------------------------------------------------------------
// Generic tiled GEMM core: Y[b][o][i] = sum_c W[o][c] * X[b][c][i] (+ bias[o])
// block = 256 threads, tile 64(o) x 64(i), k-tile 16, 4x4 register tile.
// grid = (i_tiles, o_tiles, batch)
// ---------------------------------------------------------------------------
__device__ __forceinline__ void gemm_body(
    const float* __restrict__ W, const float* __restrict__ X,
    float* __restrict__ Y, const float* __restrict__ bias,
    int K, long xstride_b, long ystride_b)
{
    __shared__ float Ws[16][64];   // [c][o]
    __shared__ float Xs[16][64];   // [c][i]

    const int b  = blockIdx.z;
    const int o0 = blockIdx.y * 64;
    const int i0 = blockIdx.x * 64;
    const float* Xb = X + (long)b * xstride_b;
    float*       Yb = Y + (long)b * ystride_b;

    const int tid = threadIdx.x;
    const int ot  = tid >> 4;     // 0..15
    const int it  = tid & 15;     // 0..15

    float acc[4][4] = {};

    for (int k0 = 0; k0 < K; k0 += 16) {
        // W tile (transposed into smem): each thread 1 float4 along c
        {
            int o = tid >> 2;                // 0..63
            int c = (tid & 3) * 4;           // 0,4,8,12
            float4 wv = *(const float4*)&W[(long)(o0 + o) * K + k0 + c];
            Ws[c + 0][o] = wv.x; Ws[c + 1][o] = wv.y;
            Ws[c + 2][o] = wv.z; Ws[c + 3][o] = wv.w;
        }
        // X tile: coalesced float4
        {
            int c = tid >> 4;                // 0..15
            int i = (tid & 15) * 4;          // 0..60
            *(float4*)&Xs[c][i] =
                *(const float4*)&Xb[(long)(k0 + c) * N_POS + i0 + i];
        }
        __syncthreads();

        #pragma unroll
        for (int kk = 0; kk < 16; kk++) {
            float4 wv = *(const float4*)&Ws[kk][ot * 4];
            float4 xv = *(const float4*)&Xs[kk][it * 4];
            float a0 = wv.x, a1 = wv.y, a2 = wv.z, a3 = wv.w;
            acc[0][0] += a0 * xv.x; acc[0][1] += a0 * xv.y; acc[0][2] += a0 * xv.z; acc[0][3] += a0 * xv.w;
            acc[1][0] += a1 * xv.x; acc[1][1] += a1 * xv.y; acc[1][2] += a1 * xv.z; acc[1][3] += a1 * xv.w;
            acc[2][0] += a2 * xv.x; acc[2][1] += a2 * xv.y; acc[2][2] += a2 * xv.z; acc[2][3] += a2 * xv.w;
            acc[3][0] += a3 * xv.x; acc[3][1] += a3 * xv.y; acc[3][2] += a3 * xv.z; acc[3][3] += a3 * xv.w;
        }
        __syncthreads();
    }

    #pragma unroll
    for (int r = 0; r < 4; r++) {
        float bb = bias ? bias[o0 + ot * 4 + r] : 0.0f;
        float4 o4;
        o4.x = acc[r][0] + bb; o4.y = acc[r][1] + bb;
        o4.z = acc[r][2] + bb; o4.w = acc[r][3] + bb;
        *(float4*)&Yb[(long)(o0 + ot * 4 + r) * N_POS + i0 + it * 4] = o4;
    }
}

// Wrapper A: qkv = w_qkv @ x ; Y is the device scratch (bound in-kernel, no
// cudaGetSymbolAddress on the host path -> kernel_launch is pure launches).
__global__ __launch_bounds__(256) void gemm_qkv_kernel(
    const float* __restrict__ W, const float* __restrict__ X)
{
    gemm_body(W, X, g_qkv, nullptr, C_IN,
              (long)C_IN * N_POS, (long)3 * HID * N_POS);
}

// Wrapper D: y = w_out @ g_att + b_out ; X is the device scratch.
__global__ __launch_bounds__(256) void gemm_out_kernel(
    const float* __restrict__ W, float* __restrict__ Y,
    const float* __restrict__ bias)
{
    gemm_body(W, g_att, Y, bias, HID,
              (long)HID * N_POS, (long)C_IN * N_POS);
}

// ---------------------------------------------------------------------------
// L2-normalize q and k over the DHEAD axis, in place in g_qkv.
// One thread per (b, s in {q,k}, h, i) position; coalesced over i.
// ---------------------------------------------------------------------------
__global__ __launch_bounds__(256) void norm_kernel()
{
    int t = blockIdx.x * blockDim.x + threadIdx.x;     // 0 .. 2*4*4*4096-1
    int i = t & (N_POS - 1);
    int r = t >> 12;
    int h = r & 3;  r >>= 2;
    int s = r & 1;
    int b = r >> 1;

    float* base = g_qkv + ((long)(b * 3 + s) * HID + h * DHEAD) * N_POS + i;

    float v[DHEAD];
    float ss = 0.0f;
    #pragma unroll
    for (int d = 0; d < DHEAD; d++) {
        v[d] = base[(long)d * N_POS];
        ss += v[d] * v[d];
    }
    float inv = 1.0f / fmaxf(sqrtf(ss), 1e-12f);
    #pragma unroll
    for (int d = 0; d < DHEAD; d++)
        base[(long)d * N_POS] = v[d] * inv;
}

// ---------------------------------------------------------------------------
// Flash attention (fixed softmax shift of +10: logits bounded by |10| since
// q,k are unit vectors  =>  no running max, no accumulator rescaling).
// Block: one (b, h, 64-query tile). 256 threads.
//   GEMM1: S[64x64] = Q^T K, thread tile 4x4 (qt=tid/16, jt=tid%16)
//   P = exp(10*S - 10) staged to smem; l accumulated in regs
//   GEMM2: O[64x32] += P V^T, thread tile 4(q) x 2(d) (dt=tid%16)
// Output: g_att[b][h*32+d][i]
// ---------------------------------------------------------------------------
__global__ __launch_bounds__(256) void attn_kernel()
{
    __shared__ float Qs[32][64];
    __shared__ float Ks[32][64];
    __shared__ float Vs[32][68];      // padded: kills bank conflict in GEMM2
    __shared__ float Ps[64][64];      // P tile; reused as Os[32][64] epilogue

    const int b   = blockIdx.z;
    const int h   = blockIdx.y;
    const int q0  = blockIdx.x * 64;
    const int tid = threadIdx.x;

    const float* qb = g_qkv + ((long)(b * 3 + 0) * HID + h * DHEAD) * N_POS;
    const float* kb = g_qkv + ((long)(b * 3 + 1) * HID + h * DHEAD) * N_POS;
    const float* vb = g_qkv + ((long)(b * 3 + 2) * HID + h * DHEAD) * N_POS;

    // Load Q tile [32 d][64 qi]
    #pragma unroll
    for (int r = 0; r < 8; r++) {
        int idx = tid + r * 256;
        int d = idx >> 6, qi = idx & 63;
        Qs[d][qi] = qb[(long)d * N_POS + q0 + qi];
    }

    const int qt = tid >> 4;    // 0..15 : query sub-tile
    const int jt = tid & 15;    // 0..15 : key sub-tile (GEMM1) / dim pair (GEMM2)

    float O[4][2] = {};
    float lsum[4] = {};

    for (int j0 = 0; j0 < N_POS; j0 += 64) {
        __syncthreads();   // prior-iter Ps/Ks/Vs readers done (also fences Q load)

        #pragma unroll
        for (int r = 0; r < 8; r++) {
            int idx = tid + r * 256;
            int d = idx >> 6, j = idx & 63;
            Ks[d][j] = kb[(long)d * N_POS + j0 + j];
            Vs[d][j] = vb[(long)d * N_POS + j0 + j];
        }
        __syncthreads();

        // ---- GEMM1: S = Q^T K ----
        float S[4][4] = {};
        #pragma unroll
        for (int d = 0; d < 32; d++) {
            float4 qv = *(const float4*)&Qs[d][qt * 4];
            float4 kv = *(const float4*)&Ks[d][jt * 4];
            S[0][0] += qv.x * kv.x; S[0][1] += qv.x * kv.y; S[0][2] += qv.x * kv.z; S[0][3] += qv.x * kv.w;
            S[1][0] += qv.y * kv.x; S[1][1] += qv.y * kv.y; S[1][2] += qv.y * kv.z; S[1][3] += qv.y * kv.w;
            S[2][0] += qv.z * kv.x; S[2][1] += qv.z * kv.y; S[2][2] += qv.z * kv.z; S[2][3] += qv.z * kv.w;
            S[3][0] += qv.w * kv.x; S[3][1] += qv.w * kv.y; S[3][2] += qv.w * kv.z; S[3][3] += qv.w * kv.w;
        }

        // ---- P = exp(10*S - 10), accumulate l, stage P ----
        #pragma unroll
        for (int r = 0; r < 4; r++) {
            float4 pv;
            pv.x = __expf(fmaf(S[r][0], SCALE, -SCALE));
            pv.y = __expf(fmaf(S[r][1], SCALE, -SCALE));
            pv.z = __expf(fmaf(S[r][2], SCALE, -SCALE));
            pv.w = __expf(fmaf(S[r][3], SCALE, -SCALE));
            lsum[r] += (pv.x + pv.y) + (pv.z + pv.w);
            *(float4*)&Ps[qt * 4 + r][jt * 4] = pv;
        }
        __syncthreads();

        // ---- GEMM2: O += P V^T  (thread: rows qt*4.., dims jt*2..) ----
        const int dt = jt;
        #pragma unroll
        for (int j = 0; j < 64; j += 4) {
            float4 v0 = *(const float4*)&Vs[dt * 2 + 0][j];
            float4 v1 = *(const float4*)&Vs[dt * 2 + 1][j];
            #pragma unroll
            for (int r = 0; r < 4; r++) {
                float4 p = *(const float4*)&Ps[qt * 4 + r][j];
                O[r][0] += p.x * v0.x + p.y * v0.y + p.z * v0.z + p.w * v0.w;
                O[r][1] += p.x * v1.x + p.y * v1.y + p.z * v1.z + p.w * v1.w;
            }
        }
    }

    // Reduce l across the 16 jt-threads of each row group (lane xor 1,2,4,8)
    #pragma unroll
    for (int m = 1; m < 16; m <<= 1) {
        #pragma unroll
        for (int r = 0; r < 4; r++)
            lsum[r] += __shfl_xor_sync(0xffffffffu, lsum[r], m);
    }

    // Normalize and stage O into smem (reuse Ps as Os[32][64]) for coalesced store
    __syncthreads();
    float (*Os)[64] = (float (*)[64])Ps;
    const int dt = jt;
    #pragma unroll
    for (int r = 0; r < 4; r++) {
        float invl = 1.0f / lsum[r];
        Os[dt * 2 + 0][qt * 4 + r] = O[r][0] * invl;
        Os[dt * 2 + 1][qt * 4 + r] = O[r][1] * invl;
    }
    __syncthreads();

    float* ob = g_att + ((long)b * HID + h * DHEAD) * N_POS + q0;
    #pragma unroll
    for (int r = 0; r < 8; r++) {
        int idx = tid + r * 256;
        int d = idx >> 6, qi = idx & 63;
        ob[(long)d * N_POS + qi] = Os[d][qi];
    }
}

// ---------------------------------------------------------------------------
extern "C" void kernel_launch(void* const* d_in, const int* in_sizes, int n_in,
                              void* d_out, int out_size)
{
    const float* x     = (const float*)d_in[0];   // [4,256,64,64]
    const float* w_qkv = (const float*)d_in[1];   // [384,256]
    const float* w_out = (const float*)d_in[2];   // [256,128]
    const float* b_out = (const float*)d_in[3];   // [256]
    float* y = (float*)d_out;                     // [4,256,64,64]

    // A: qkv = w_qkv @ x       [384 x 256] . [256 x 4096] per batch
    {
        dim3 grid(N_POS / 64, (3 * HID) / 64, BATCH);
        gemm_qkv_kernel<<<grid, 256>>>(w_qkv, x);
    }
    // B: L2-normalize q, k
    {
        int total = 2 * BATCH * HEADS * N_POS;    // 131072
        norm_kernel<<<total / 256, 256>>>();
    }
    // C: flash attention
    {
        dim3 grid(N_POS / 64, HEADS, BATCH);
        attn_kernel<<<grid, 256>>>();
    }
    // D: y = w_out @ att + b_out   [256 x 128] . [128 x 4096] per batch
    {
        dim3 grid(N_POS / 64, C_IN / 64, BATCH);
        gemm_out_kernel<<<grid, 256>>>(w_out, y, b_out);
    }
}

// round 5
// speedup vs baseline: 2.3095x; 2.3095x over previous
#include <cuda_runtime.h>
#include <cstdint>

#define N_POS   4096
#define HEADS   4
#define DHEAD   32
#define C_IN    256
#define HID     128          // HEADS*DHEAD
#define BATCH   4
#define SCALE   10.0f

// Scratch (no cudaMalloc allowed): qkv [b][3*128][n], attn-out [b][128][n]
__device__ float g_qkv[(size_t)BATCH * 3 * HID * N_POS];   // 25.2 MB
__device__ float g_att[(size_t)BATCH * HID * N_POS];       //  8.4 MB

// ---------------------------------------------------------------------------
// Generic tiled GEMM core: Y[b][o][i] = sum_c W[o][c] * X[b][c][i] (+ bias[o])
// block = 256 threads, tile 64(o) x 64(i), k-tile 16, 4x4 register tile.
// ---------------------------------------------------------------------------
__device__ __forceinline__ void gemm_body(
    const float* __restrict__ W, const float* __restrict__ X,
    float* __restrict__ Y, const float* __restrict__ bias,
    int K, long xstride_b, long ystride_b)
{
    __shared__ float Ws[16][64];   // [c][o]
    __shared__ float Xs[16][64];   // [c][i]

    const int b  = blockIdx.z;
    const int o0 = blockIdx.y * 64;
    const int i0 = blockIdx.x * 64;
    const float* Xb = X + (long)b * xstride_b;
    float*       Yb = Y + (long)b * ystride_b;

    const int tid = threadIdx.x;
    const int ot  = tid >> 4;     // 0..15
    const int it  = tid & 15;     // 0..15

    float acc[4][4] = {};

    for (int k0 = 0; k0 < K; k0 += 16) {
        {
            int o = tid >> 2;                // 0..63
            int c = (tid & 3) * 4;           // 0,4,8,12
            float4 wv = *(const float4*)&W[(long)(o0 + o) * K + k0 + c];
            Ws[c + 0][o] = wv.x; Ws[c + 1][o] = wv.y;
            Ws[c + 2][o] = wv.z; Ws[c + 3][o] = wv.w;
        }
        {
            int c = tid >> 4;                // 0..15
            int i = (tid & 15) * 4;          // 0..60
            *(float4*)&Xs[c][i] =
                *(const float4*)&Xb[(long)(k0 + c) * N_POS + i0 + i];
        }
        __syncthreads();

        #pragma unroll
        for (int kk = 0; kk < 16; kk++) {
            float4 wv = *(const float4*)&Ws[kk][ot * 4];
            float4 xv = *(const float4*)&Xs[kk][it * 4];
            float a0 = wv.x, a1 = wv.y, a2 = wv.z, a3 = wv.w;
            acc[0][0] += a0 * xv.x; acc[0][1] += a0 * xv.y; acc[0][2] += a0 * xv.z; acc[0][3] += a0 * xv.w;
            acc[1][0] += a1 * xv.x; acc[1][1] += a1 * xv.y; acc[1][2] += a1 * xv.z; acc[1][3] += a1 * xv.w;
            acc[2][0] += a2 * xv.x; acc[2][1] += a2 * xv.y; acc[2][2] += a2 * xv.z; acc[2][3] += a2 * xv.w;
            acc[3][0] += a3 * xv.x; acc[3][1] += a3 * xv.y; acc[3][2] += a3 * xv.z; acc[3][3] += a3 * xv.w;
        }
        __syncthreads();
    }

    #pragma unroll
    for (int r = 0; r < 4; r++) {
        float bb = bias ? bias[o0 + ot * 4 + r] : 0.0f;
        float4 o4;
        o4.x = acc[r][0] + bb; o4.y = acc[r][1] + bb;
        o4.z = acc[r][2] + bb; o4.w = acc[r][3] + bb;
        *(float4*)&Yb[(long)(o0 + ot * 4 + r) * N_POS + i0 + it * 4] = o4;
    }
}

__global__ __launch_bounds__(256) void gemm_qkv_kernel(
    const float* __restrict__ W, const float* __restrict__ X)
{
    gemm_body(W, X, g_qkv, nullptr, C_IN,
              (long)C_IN * N_POS, (long)3 * HID * N_POS);
}

__global__ __launch_bounds__(256) void gemm_out_kernel(
    const float* __restrict__ W, float* __restrict__ Y,
    const float* __restrict__ bias)
{
    gemm_body(W, g_att, Y, bias, HID,
              (long)HID * N_POS, (long)C_IN * N_POS);
}

// ---------------------------------------------------------------------------
// L2-normalize q and k over the DHEAD axis, in place in g_qkv.
// ---------------------------------------------------------------------------
__global__ __launch_bounds__(256) void norm_kernel()
{
    int t = blockIdx.x * blockDim.x + threadIdx.x;
    int i = t & (N_POS - 1);
    int r = t >> 12;
    int h = r & 3;  r >>= 2;
    int s = r & 1;
    int b = r >> 1;

    float* base = g_qkv + ((long)(b * 3 + s) * HID + h * DHEAD) * N_POS + i;

    float v[DHEAD];
    float ss = 0.0f;
    #pragma unroll
    for (int d = 0; d < DHEAD; d++) {
        v[d] = base[(long)d * N_POS];
        ss += v[d] * v[d];
    }
    float inv = 1.0f / fmaxf(sqrtf(ss), 1e-12f);
    #pragma unroll
    for (int d = 0; d < DHEAD; d++)
        base[(long)d * N_POS] = v[d] * inv;
}

// ---------------------------------------------------------------------------
// Tensor-core flash attention (tf32 mma.sync m16n8k8, HMMA pipe).
// Fixed softmax shift +10 (q,k unit vectors => logits in [-10,10]) => no
// online max, no rescale; single l-division at the end.
//
// Block = (b, h, 64-query tile), 256 threads = 8 warps.
//   GEMM1: S[64x64] = Q[64x32] K'[32x64]; warp grid 4(q) x 2(j): 4 n-tiles, 4 k-steps
//   P = exp(10S-10) -> tf32 -> Ps smem; l accumulated in regs
//   GEMM2: O[64x32] += P[64x64] V'[64x32]; warp grid 4(q) x 2(d): 2 n-tiles, 8 k-steps
// Smem strides padded for conflict-free fragment LDS:
//   Qs/Ks stride 72 (bank = 8*tig+gid, all distinct)
//   Vs/Ps stride 68 (bank = 4*gid+tig, all distinct)
// ---------------------------------------------------------------------------
#define QS_STR 72
#define KS_STR 72
#define VS_STR 68
#define PS_STR 68

__device__ __forceinline__ uint32_t f2tf(float x) {
    uint32_t r;
    asm("cvt.rna.tf32.f32 %0, %1;" : "=r"(r) : "f"(x));
    return r;
}

__device__ __forceinline__ void mma_tf32(float d[4], const uint32_t a[4],
                                         const uint32_t b[2]) {
    asm volatile(
        "mma.sync.aligned.m16n8k8.row.col.f32.tf32.tf32.f32 "
        "{%0,%1,%2,%3}, {%4,%5,%6,%7}, {%8,%9}, {%0,%1,%2,%3};"
        : "+f"(d[0]), "+f"(d[1]), "+f"(d[2]), "+f"(d[3])
        : "r"(a[0]), "r"(a[1]), "r"(a[2]), "r"(a[3]), "r"(b[0]), "r"(b[1]));
}

__global__ __launch_bounds__(256) void attn_tc_kernel()
{
    __shared__ uint32_t Qs[32 * QS_STR];
    __shared__ uint32_t Ks[32 * KS_STR];
    __shared__ uint32_t Vs[32 * VS_STR];
    __shared__ uint32_t Ps[64 * PS_STR];   // reused as Os[32][68] in epilogue
    __shared__ float    sh_l[64];

    const int b   = blockIdx.z;
    const int h   = blockIdx.y;
    const int q0  = blockIdx.x * 64;
    const int tid = threadIdx.x;
    const int wid  = tid >> 5;
    const int lane = tid & 31;
    const int gid  = lane >> 2;   // 0..7
    const int tig  = lane & 3;    // 0..3

    const float* qb = g_qkv + ((long)(b * 3 + 0) * HID + h * DHEAD) * N_POS;
    const float* kb = g_qkv + ((long)(b * 3 + 1) * HID + h * DHEAD) * N_POS;
    const float* vb = g_qkv + ((long)(b * 3 + 2) * HID + h * DHEAD) * N_POS;

    // Load Q tile [32 d][64 q], rounded to tf32
    #pragma unroll
    for (int r = 0; r < 8; r++) {
        int idx = tid + r * 256;
        int d = idx >> 6, qi = idx & 63;
        Qs[d * QS_STR + qi] = f2tf(qb[(long)d * N_POS + q0 + qi]);
    }
    if (tid < 64) sh_l[tid] = 0.0f;

    const int wq = wid >> 1;   // 0..3 : 16-row q group
    const int wn = wid & 1;    // 0..1 : j-half (GEMM1) / d-half (GEMM2)

    float O[2][4] = {};        // persistent PV accumulators
    float l_lo = 0.0f, l_hi = 0.0f;

    for (int j0 = 0; j0 < N_POS; j0 += 64) {
        __syncthreads();   // previous-iter consumers done (also fences Q/sh_l init)

        #pragma unroll
        for (int r = 0; r < 8; r++) {
            int idx = tid + r * 256;
            int d = idx >> 6, j = idx & 63;
            Ks[d * KS_STR + j] = f2tf(kb[(long)d * N_POS + j0 + j]);
            Vs[d * VS_STR + j] = f2tf(vb[(long)d * N_POS + j0 + j]);
        }
        __syncthreads();

        // ---- GEMM1: S = Q K' ----
        float S[4][4] = {};
        #pragma unroll
        for (int kk = 0; kk < 4; kk++) {
            uint32_t a[4];
            const int row = wq * 16 + gid;
            const int c0  = kk * 8 + tig;
            a[0] = Qs[c0 * QS_STR + row];
            a[1] = Qs[c0 * QS_STR + row + 8];
            a[2] = Qs[(c0 + 4) * QS_STR + row];
            a[3] = Qs[(c0 + 4) * QS_STR + row + 8];
            #pragma unroll
            for (int nt = 0; nt < 4; nt++) {
                const int col = wn * 32 + nt * 8 + gid;
                uint32_t bb[2];
                bb[0] = Ks[c0 * KS_STR + col];
                bb[1] = Ks[(c0 + 4) * KS_STR + col];
                mma_tf32(S[nt], a, bb);
            }
        }

        // ---- P = exp(10S - 10) -> tf32 -> Ps ; accumulate l ----
        #pragma unroll
        for (int nt = 0; nt < 4; nt++) {
            float p0 = __expf(fmaf(S[nt][0], SCALE, -SCALE));
            float p1 = __expf(fmaf(S[nt][1], SCALE, -SCALE));
            float p2 = __expf(fmaf(S[nt][2], SCALE, -SCALE));
            float p3 = __expf(fmaf(S[nt][3], SCALE, -SCALE));
            l_lo += p0 + p1;
            l_hi += p2 + p3;
            const int row = wq * 16 + gid;
            const int col = wn * 32 + nt * 8 + 2 * tig;
            uint64_t lo2 = (uint64_t)f2tf(p0) | ((uint64_t)f2tf(p1) << 32);
            uint64_t hi2 = (uint64_t)f2tf(p2) | ((uint64_t)f2tf(p3) << 32);
            *(uint64_t*)&Ps[row * PS_STR + col]       = lo2;
            *(uint64_t*)&Ps[(row + 8) * PS_STR + col] = hi2;
        }
        __syncthreads();

        // ---- GEMM2: O += P V' ----
        #pragma unroll
        for (int kk = 0; kk < 8; kk++) {
            uint32_t a[4];
            const int row = wq * 16 + gid;
            const int c0  = kk * 8 + tig;
            a[0] = Ps[row * PS_STR + c0];
            a[1] = Ps[(row + 8) * PS_STR + c0];
            a[2] = Ps[row * PS_STR + c0 + 4];
            a[3] = Ps[(row + 8) * PS_STR + c0 + 4];
            #pragma unroll
            for (int nt = 0; nt < 2; nt++) {
                const int dcol = wn * 16 + nt * 8 + gid;
                uint32_t bb[2];
                bb[0] = Vs[dcol * VS_STR + c0];
                bb[1] = Vs[dcol * VS_STR + c0 + 4];
                mma_tf32(O[nt], a, bb);
            }
        }
    }

    // ---- reduce l: over tig (quad shuffles), then across wn via shared atomics
    l_lo += __shfl_xor_sync(0xffffffffu, l_lo, 1);
    l_lo += __shfl_xor_sync(0xffffffffu, l_lo, 2);
    l_hi += __shfl_xor_sync(0xffffffffu, l_hi, 1);
    l_hi += __shfl_xor_sync(0xffffffffu, l_hi, 2);
    if (tig == 0) {
        atomicAdd(&sh_l[wq * 16 + gid],     l_lo);
        atomicAdd(&sh_l[wq * 16 + gid + 8], l_hi);
    }
    __syncthreads();   // atomics done; also: all GEMM2 reads of Ps complete

    const float invl_lo = 1.0f / sh_l[wq * 16 + gid];
    const float invl_hi = 1.0f / sh_l[wq * 16 + gid + 8];

    // ---- normalize + transpose through smem (reuse Ps as Os[32][68]) ----
    float* Os = (float*)Ps;
    #pragma unroll
    for (int nt = 0; nt < 2; nt++) {
        const int dc = wn * 16 + nt * 8 + 2 * tig;
        const int qr = wq * 16 + gid;
        Os[dc * PS_STR + qr]           = O[nt][0] * invl_lo;
        Os[(dc + 1) * PS_STR + qr]     = O[nt][1] * invl_lo;
        Os[dc * PS_STR + qr + 8]       = O[nt][2] * invl_hi;
        Os[(dc + 1) * PS_STR + qr + 8] = O[nt][3] * invl_hi;
    }
    __syncthreads();

    float* ob = g_att + ((long)b * HID + h * DHEAD) * N_POS + q0;
    #pragma unroll
    for (int r = 0; r < 8; r++) {
        int idx = tid + r * 256;
        int d = idx >> 6, qi = idx & 63;
        ob[(long)d * N_POS + qi] = Os[d * PS_STR + qi];
    }
}

// ---------------------------------------------------------------------------
extern "C" void kernel_launch(void* const* d_in, const int* in_sizes, int n_in,
                              void* d_out, int out_size)
{
    const float* x     = (const float*)d_in[0];   // [4,256,64,64]
    const float* w_qkv = (const float*)d_in[1];   // [384,256]
    const float* w_out = (const float*)d_in[2];   // [256,128]
    const float* b_out = (const float*)d_in[3];   // [256]
    float* y = (float*)d_out;                     // [4,256,64,64]

    // A: qkv = w_qkv @ x
    {
        dim3 grid(N_POS / 64, (3 * HID) / 64, BATCH);
        gemm_qkv_kernel<<<grid, 256>>>(w_qkv, x);
    }
    // B: L2-normalize q, k
    {
        int total = 2 * BATCH * HEADS * N_POS;
        norm_kernel<<<total / 256, 256>>>();
    }
    // C: tensor-core flash attention
    {
        dim3 grid(N_POS / 64, HEADS, BATCH);
        attn_tc_kernel<<<grid, 256>>>();
    }
    // D: y = w_out @ att + b_out
    {
        dim3 grid(N_POS / 64, C_IN / 64, BATCH);
        gemm_out_kernel<<<grid, 256>>>(w_out, y, b_out);
    }
}